// round 14
// baseline (speedup 1.0000x reference)
#include <cuda_runtime.h>
#include <cuda_fp16.h>
#include <cstdint>

#define B_SZ 8
#define NPTS 16384
#define MSRC 1024
#define C1   128
#define C2   256
#define CIN  384
#define CO   256
#define BN_EPS 1e-5f

// ---------------------------------------------------------------------------
// Scratch (allocation-free)
// ---------------------------------------------------------------------------
__device__ __align__(256) float  g_Zt [(size_t)B_SZ * MSRC * CO];
__device__ __align__(256) int4   g_nni[(size_t)B_SZ * NPTS];
__device__ __align__(256) float4 g_nnw[(size_t)B_SZ * NPTS];
__device__ __align__(256) __half g_W0 [CO * C1];
__device__ __align__(256) __half g_W1 [CO * CO];
__device__ __align__(256) __half g_T  [(size_t)B_SZ * NPTS * C1];   // tfeat^T fp16
__device__ __align__(256) __half g_Y0 [(size_t)B_SZ * NPTS * CO];   // Y0^T fp16

// ---------------------------------------------------------------------------
// PTX helpers (sm_100-safe)
// ---------------------------------------------------------------------------
__device__ __forceinline__ uint32_t smem_u32(const void* p) {
    uint32_t a;
    asm("{ .reg .u64 t; cvta.to.shared.u64 t, %1; cvt.u32.u64 %0, t; }" : "=r"(a) : "l"(p));
    return a;
}
#define CP16(dst, src) \
    asm volatile("cp.async.cg.shared.global [%0], [%1], 16;" :: "r"(dst), "l"(src))
#define CP_COMMIT() asm volatile("cp.async.commit_group;" ::: "memory")
#define CP_WAIT(n)  asm volatile("cp.async.wait_group %0;" :: "n"(n) : "memory")

#define LDSM4(r, addr) \
    asm volatile("ldmatrix.sync.aligned.m8n8.x4.shared.b16 {%0,%1,%2,%3}, [%4];" \
        : "=r"((r)[0]), "=r"((r)[1]), "=r"((r)[2]), "=r"((r)[3]) : "r"(addr))

#define MMA_F16(d, a, b0, b1) \
    asm volatile("mma.sync.aligned.m16n8k16.row.col.f32.f16.f16.f32 " \
        "{%0,%1,%2,%3}, {%4,%5,%6,%7}, {%8,%9}, {%0,%1,%2,%3};" \
        : "+f"((d)[0]), "+f"((d)[1]), "+f"((d)[2]), "+f"((d)[3]) \
        : "r"((a)[0]), "r"((a)[1]), "r"((a)[2]), "r"((a)[3]), "r"(b0), "r"(b1))

// ---------------------------------------------------------------------------
// three_nn: 2 target points per thread. Grid: (NPTS/512, B), 256 threads.
// ---------------------------------------------------------------------------
__global__ void __launch_bounds__(256)
three_nn_kernel(const float* __restrict__ target, const float* __restrict__ source,
                int4* __restrict__ nni, float4* __restrict__ nnw)
{
    const int b = blockIdx.y, t = threadIdx.x;
    const int ia = blockIdx.x * 512 + t;
    const int ib = ia + 256;
    __shared__ float4 s[MSRC];
    const float* src = source + (size_t)b * MSRC * 3;
    for (int j = t; j < MSRC; j += 256) {
        const float x = src[j * 3 + 0], y = src[j * 3 + 1], z = src[j * 3 + 2];
        s[j] = make_float4(x, y, z, x * x + y * y + z * z);
    }
    __syncthreads();

    const float* tpa = target + ((size_t)b * NPTS + ia) * 3;
    const float* tpb = target + ((size_t)b * NPTS + ib) * 3;
    const float pax = tpa[0], pay = tpa[1], paz = tpa[2];
    const float pbx = tpb[0], pby = tpb[1], pbz = tpb[2];
    const float qax = -2.0f * pax, qay = -2.0f * pay, qaz = -2.0f * paz;
    const float qbx = -2.0f * pbx, qby = -2.0f * pby, qbz = -2.0f * pbz;

    float a0 = 3.4e38f, a1 = 3.4e38f, a2 = 3.4e38f;
    float f0 = 3.4e38f, f1 = 3.4e38f, f2 = 3.4e38f;
    int   ja0 = 0, ja1 = 0, ja2 = 0, jb0 = 0, jb1 = 0, jb2 = 0;
    #pragma unroll 4
    for (int j = 0; j < MSRC; j++) {
        const float4 v = s[j];
        const float ea = fmaf(qax, v.x, fmaf(qay, v.y, fmaf(qaz, v.z, v.w)));
        const float eb = fmaf(qbx, v.x, fmaf(qby, v.y, fmaf(qbz, v.z, v.w)));
        if (ea < a0)      { a2 = a1; ja2 = ja1; a1 = a0; ja1 = ja0; a0 = ea; ja0 = j; }
        else if (ea < a1) { a2 = a1; ja2 = ja1; a1 = ea; ja1 = j; }
        else if (ea < a2) { a2 = ea; ja2 = j; }
        if (eb < f0)      { f2 = f1; jb2 = jb1; f1 = f0; jb1 = jb0; f0 = eb; jb0 = j; }
        else if (eb < f1) { f2 = f1; jb2 = jb1; f1 = eb; jb1 = j; }
        else if (eb < f2) { f2 = eb; jb2 = j; }
    }
    {
        float d[3]; const int jj[3] = {ja0, ja1, ja2};
        #pragma unroll
        for (int k = 0; k < 3; k++) {
            const float4 v = s[jj[k]];
            const float dx = pax - v.x, dy = pay - v.y, dz = paz - v.z;
            d[k] = dx * dx + dy * dy + dz * dz;
        }
        const float r0 = 1.0f / (d[0] + 1e-8f), r1 = 1.0f / (d[1] + 1e-8f), r2 = 1.0f / (d[2] + 1e-8f);
        const float rs = 1.0f / (r0 + r1 + r2);
        nni[(size_t)b * NPTS + ia] = make_int4(ja0, ja1, ja2, 0);
        nnw[(size_t)b * NPTS + ia] = make_float4(r0 * rs, r1 * rs, r2 * rs, 0.0f);
    }
    {
        float d[3]; const int jj[3] = {jb0, jb1, jb2};
        #pragma unroll
        for (int k = 0; k < 3; k++) {
            const float4 v = s[jj[k]];
            const float dx = pbx - v.x, dy = pby - v.y, dz = pbz - v.z;
            d[k] = dx * dx + dy * dy + dz * dz;
        }
        const float r0 = 1.0f / (d[0] + 1e-8f), r1 = 1.0f / (d[1] + 1e-8f), r2 = 1.0f / (d[2] + 1e-8f);
        const float rs = 1.0f / (r0 + r1 + r2);
        nni[(size_t)b * NPTS + ib] = make_int4(jb0, jb1, jb2, 0);
        nnw[(size_t)b * NPTS + ib] = make_float4(r0 * rs, r1 * rs, r2 * rs, 0.0f);
    }
}

// ---------------------------------------------------------------------------
// Zt = (w0[:, :256] @ sfeat)^T per batch (fp32 — keeps interp path exact)
// ---------------------------------------------------------------------------
__global__ void __launch_bounds__(256, 2)
zt_kernel(const float* __restrict__ w0, const float* __restrict__ sfeat, float* __restrict__ Zt)
{
    constexpr int BK = 16, TM = 8, TN = 8;
    __shared__ float Ss[BK][128];
    __shared__ float Ws[BK][128];
    const int b = blockIdx.z, J0 = blockIdx.x * 128, O0 = blockIdx.y * 128;
    const float* sf = sfeat + (size_t)b * C2 * MSRC;
    const int tid = threadIdx.x;
    const int rowO = tid >> 2, colK = (tid & 3) * 4;
    const int rowK = tid >> 5, colJ = (tid & 31) * 4;
    const int tj = (tid >> 4) * TM, to = (tid & 15) * TN;
    float acc[TM][TN];
    #pragma unroll
    for (int i = 0; i < TM; i++)
        #pragma unroll
        for (int j = 0; j < TN; j++) acc[i][j] = 0.0f;
    for (int k0 = 0; k0 < C2; k0 += BK) {
        #pragma unroll
        for (int p = 0; p < 2; p++) {
            const int r = rowO + p * 64;
            const float4 v = *(const float4*)(w0 + (size_t)(O0 + r) * CIN + k0 + colK);
            Ws[colK + 0][r] = v.x; Ws[colK + 1][r] = v.y;
            Ws[colK + 2][r] = v.z; Ws[colK + 3][r] = v.w;
        }
        #pragma unroll
        for (int p = 0; p < 2; p++) {
            const int r = rowK + p * 8;
            *(float4*)&Ss[r][colJ] = *(const float4*)(sf + (size_t)(k0 + r) * MSRC + J0 + colJ);
        }
        __syncthreads();
        #pragma unroll
        for (int kk = 0; kk < BK; kk++) {
            float a[TM], w[TN];
            #pragma unroll
            for (int i = 0; i < TM; i += 4) *(float4*)&a[i] = *(const float4*)&Ss[kk][tj + i];
            #pragma unroll
            for (int j = 0; j < TN; j += 4) *(float4*)&w[j] = *(const float4*)&Ws[kk][to + j];
            #pragma unroll
            for (int i = 0; i < TM; i++)
                #pragma unroll
                for (int j = 0; j < TN; j++) acc[i][j] = fmaf(a[i], w[j], acc[i][j]);
        }
        __syncthreads();
    }
    float* Zb = Zt + (size_t)b * MSRC * CO;
    #pragma unroll
    for (int i = 0; i < TM; i++)
        #pragma unroll
        for (int j = 0; j < TN; j += 4) {
            float4 v = make_float4(acc[i][j], acc[i][j+1], acc[i][j+2], acc[i][j+3]);
            *(float4*)(Zb + (size_t)(J0 + tj + i) * CO + O0 + to + j) = v;
        }
}

// ---------------------------------------------------------------------------
// Merged weight convert (W0 slice + W1, single fp16 planes)
// ---------------------------------------------------------------------------
__global__ void __launch_bounds__(256)
conv_w2_kernel(const float* __restrict__ w0, const float* __restrict__ w1,
               __half* __restrict__ W0, __half* __restrict__ W1)
{
    const int idx = blockIdx.x * 256 + threadIdx.x;
    if (idx < CO * C1) {
        const int o = idx / C1, k = idx % C1;
        W0[idx] = __float2half_rn(w0[(size_t)o * CIN + C2 + k]);
    } else {
        const int j = idx - CO * C1;
        if (j < CO * CO) {
            const int o = j / CO, k = j % CO;
            W1[j] = __float2half_rn(w1[(size_t)o * CO + k]);
        }
    }
}

// ---------------------------------------------------------------------------
// tfeat transpose: (B,C1,N) fp32 -> (B,N,C1) fp16
// ---------------------------------------------------------------------------
__global__ void __launch_bounds__(256)
tfeat_t_kernel(const float* __restrict__ tfeat, __half* __restrict__ T)
{
    __shared__ float sm[32][33];
    const int b = blockIdx.z;
    const int n0 = blockIdx.x * 32, c0 = blockIdx.y * 32;
    const int tx = threadIdx.x & 31, ty = threadIdx.x >> 5;
    const float* src = tfeat + (size_t)b * C1 * NPTS;
    #pragma unroll
    for (int i = 0; i < 4; i++) {
        const int c = ty + i * 8;
        sm[c][tx] = src[(size_t)(c0 + c) * NPTS + n0 + tx];
    }
    __syncthreads();
    #pragma unroll
    for (int i = 0; i < 4; i++) {
        const int n = ty + i * 8;
        T[((size_t)b * NPTS + n0 + n) * C1 + c0 + tx] = __float2half_rn(sm[tx][n]);
    }
}

// ---------------------------------------------------------------------------
// Layer 0 (NEW): 512 threads, CTA tile 128m x 256n, FULL K=128 resident in
// smem (single buffer, one cp.async batch, sync-free 8-step mainloop).
// 16 warps: wm = wid>>2 (4 m-slices of 32), wn = wid&3 (4 n-slices of 64).
// Row stride 272 B (== 16 mod 128 -> ldmatrix conflict-free).
// Epilogue: two 128-n halves through bounce (overlays dead B tile) ->
// gather(Zt) + BN + ReLU -> Y0^T fp16.
// Grid: (NPTS/256, CO/128, B).
// ---------------------------------------------------------------------------
__global__ void __launch_bounds__(512, 2)
mma_layer0_kernel(const __half* __restrict__ W0, const __half* __restrict__ T,
                  __half* __restrict__ Y0out,
                  const float* __restrict__ gam, const float* __restrict__ bet,
                  const float* __restrict__ mu,  const float* __restrict__ var,
                  const int4* __restrict__ nni, const float4* __restrict__ nnw,
                  const float* __restrict__ Zt)
{
    constexpr int RS   = 272;             // row stride bytes (128 halves payload)
    constexpr int BOFF = 0;               // B tile: 256 x 272 = 69632
    constexpr int AOFF = 69632;           // A tile: 128 x 272 = 34816 (total 104448)
    extern __shared__ __align__(16) char smem[];
    const uint32_t sb = smem_u32(smem);

    const int tid = threadIdx.x, lane = tid & 31, wid = tid >> 5;
    const int wm = wid >> 2, wn = wid & 3;
    const int b = blockIdx.z, n0 = blockIdx.x * 256, m0 = blockIdx.y * 128;
    const size_t bn = (size_t)b * NPTS;

    const __half* A_g = W0 + (size_t)m0 * C1;
    const __half* B_g = T + (bn + n0) * C1;

    // ---- single prologue: load full A (128x128) + full B (256x128) --------
    // B: 256 rows x 16 slots of 16B = 4096 cps -> 8/thread
    #pragma unroll
    for (int it = 0; it < 8; it++) {
        const int idx = tid + it * 512;
        const int r = idx >> 4, sl = idx & 15;
        CP16(sb + BOFF + r * RS + sl * 16, B_g + (size_t)r * C1 + sl * 8);
    }
    // A: 128 rows x 16 slots -> 4/thread
    #pragma unroll
    for (int it = 0; it < 4; it++) {
        const int idx = tid + it * 512;
        const int r = idx >> 4, sl = idx & 15;
        CP16(sb + AOFF + r * RS + sl * 16, A_g + (size_t)r * C1 + sl * 8);
    }
    CP_COMMIT();

    float acc[2][8][4];
    #pragma unroll
    for (int i = 0; i < 2; i++)
        #pragma unroll
        for (int j = 0; j < 8; j++)
            #pragma unroll
            for (int q = 0; q < 4; q++) acc[i][j][q] = 0.0f;

    CP_WAIT(0);
    __syncthreads();

    // ---- sync-free mainloop: 8 k-steps of 16 -------------------------------
    #pragma unroll
    for (int kk = 0; kk < 8; kk++) {
        uint32_t ah[2][4];
        #pragma unroll
        for (int mt = 0; mt < 2; mt++) {
            const uint32_t ad = sb + AOFF
                + (uint32_t)((wm * 32 + mt * 16 + (lane & 15)) * RS
                             + (kk * 16 + ((lane >> 4) << 3)) * 2);
            LDSM4(ah[mt], ad);
        }
        #pragma unroll
        for (int ng = 0; ng < 4; ng++) {
            uint32_t bh[4];
            const uint32_t bd = sb + BOFF
                + (uint32_t)((wn * 64 + ng * 16 + (lane & 7) + ((lane >> 4) << 3)) * RS
                             + (kk * 16 + (((lane >> 3) & 1) << 3)) * 2);
            LDSM4(bh, bd);
            #pragma unroll
            for (int mt = 0; mt < 2; mt++)
                #pragma unroll
                for (int hh = 0; hh < 2; hh++)
                    MMA_F16(acc[mt][ng * 2 + hh], ah[mt], bh[2 * hh], bh[2 * hh + 1]);
        }
    }
    __syncthreads();   // all B/A reads done before bounce overlays B

    // ---- epilogue: two 128-n halves --------------------------------------
    float* S = (float*)smem;   // 128 x 132 x 4 = 67584 <= 69632 (B region)
    const float* Zb = Zt + (size_t)b * MSRC * CO;
    #pragma unroll
    for (int h = 0; h < 2; h++) {
        if ((wn >> 1) == h) {
            const int ol = wm * 32;
            #pragma unroll
            for (int mt = 0; mt < 2; mt++) {
                const int oo = ol + mt * 16 + (lane >> 2);
                #pragma unroll
                for (int j = 0; j < 8; j++) {
                    const int nl = (wn & 1) * 64 + j * 8 + (lane & 3) * 2;
                    S[(nl + 0) * 132 + oo]     = acc[mt][j][0];
                    S[(nl + 1) * 132 + oo]     = acc[mt][j][1];
                    S[(nl + 0) * 132 + oo + 8] = acc[mt][j][2];
                    S[(nl + 1) * 132 + oo + 8] = acc[mt][j][3];
                }
            }
        }
        __syncthreads();
        #pragma unroll 2
        for (int it = 0; it < 8; it++) {
            const int item = tid + it * 512;
            const int nl = item >> 5, o4 = (item & 31) * 4;
            const int n = n0 + h * 128 + nl, o = m0 + o4;
            float4 v = *(float4*)(S + nl * 132 + o4);
            const int4   ji = nni[bn + n];
            const float4 jw = nnw[bn + n];
            const float4 z0 = *(const float4*)(Zb + (size_t)ji.x * CO + o);
            const float4 z1 = *(const float4*)(Zb + (size_t)ji.y * CO + o);
            const float4 z2 = *(const float4*)(Zb + (size_t)ji.z * CO + o);
            v.x += jw.x * z0.x + jw.y * z1.x + jw.z * z2.x;
            v.y += jw.x * z0.y + jw.y * z1.y + jw.z * z2.y;
            v.z += jw.x * z0.z + jw.y * z1.z + jw.z * z2.z;
            v.w += jw.x * z0.w + jw.y * z1.w + jw.z * z2.w;
            const float4 g4 = *(const float4*)(gam + o);
            const float4 b4 = *(const float4*)(bet + o);
            const float4 m4 = *(const float4*)(mu  + o);
            const float4 q4 = *(const float4*)(var + o);
            const float sx = g4.x * rsqrtf(q4.x + BN_EPS);
            const float sy = g4.y * rsqrtf(q4.y + BN_EPS);
            const float sz = g4.z * rsqrtf(q4.z + BN_EPS);
            const float sw = g4.w * rsqrtf(q4.w + BN_EPS);
            union { __half hh[4]; uint2 u; } H;
            H.hh[0] = __float2half_rn(fmaxf(fmaf(v.x, sx, b4.x - m4.x * sx), 0.0f));
            H.hh[1] = __float2half_rn(fmaxf(fmaf(v.y, sy, b4.y - m4.y * sy), 0.0f));
            H.hh[2] = __float2half_rn(fmaxf(fmaf(v.z, sz, b4.z - m4.z * sz), 0.0f));
            H.hh[3] = __float2half_rn(fmaxf(fmaf(v.w, sw, b4.w - m4.w * sw), 0.0f));
            *(uint2*)(Y0out + (bn + n) * CO + o) = H.u;
        }
        __syncthreads();
    }
}

// ---------------------------------------------------------------------------
// Layer 1: unchanged (measured 74.9 us). fp16 single-pass, CTA 128x128,
// BK=64, cp.async double buffer, 2 CTAs/SM.
// ---------------------------------------------------------------------------
__global__ void __launch_bounds__(256, 2)
mma_layer1_kernel(const __half* __restrict__ W, const __half* __restrict__ X,
                  float* __restrict__ outF,
                  const float* __restrict__ gam, const float* __restrict__ bet,
                  const float* __restrict__ mu,  const float* __restrict__ var)
{
    constexpr int KW  = CO;
    constexpr int KC  = KW / 64;
    constexpr int TS  = 128 * 144;
    constexpr int BUF = 2 * TS;
    extern __shared__ __align__(16) char smem[];
    const uint32_t sb = smem_u32(smem);

    const int tid = threadIdx.x, lane = tid & 31, wid = tid >> 5;
    const int wm = wid >> 1, wn = wid & 1;
    const int b = blockIdx.z, n0 = blockIdx.x * 128, m0 = blockIdx.y * 128;

    const __half* A_g = W + (size_t)m0 * KW;
    const __half* B_g = X + ((size_t)b * NPTS + n0) * KW;

    const int lr = tid >> 3;
    const int lc = (tid & 7) * 8;

    float acc[2][8][4];
    #pragma unroll
    for (int i = 0; i < 2; i++)
        #pragma unroll
        for (int j = 0; j < 8; j++)
            #pragma unroll
            for (int q = 0; q < 4; q++) acc[i][j][q] = 0.0f;

    #pragma unroll
    for (int it = 0; it < 4; it++) {
        const int r = lr + it * 32;
        const uint32_t so = (uint32_t)(r * 144 + lc * 2);
        CP16(sb + so,      A_g + (size_t)r * KW + lc);
        CP16(sb + TS + so, B_g + (size_t)r * KW + lc);
    }
    CP_COMMIT();

    for (int c = 0; c < KC; c++) {
        if (c + 1 < KC) {
            const int k0 = (c + 1) * 64;
            const uint32_t bufo = (uint32_t)(((c + 1) & 1) * BUF);
            #pragma unroll
            for (int it = 0; it < 4; it++) {
                const int r = lr + it * 32;
                const uint32_t so = bufo + (uint32_t)(r * 144 + lc * 2);
                CP16(sb + so,      A_g + (size_t)r * KW + k0 + lc);
                CP16(sb + TS + so, B_g + (size_t)r * KW + k0 + lc);
            }
            CP_COMMIT();
            CP_WAIT(1);
        } else {
            CP_WAIT(0);
        }
        __syncthreads();

        const uint32_t base = sb + (uint32_t)((c & 1) * BUF);
        #pragma unroll
        for (int kk = 0; kk < 4; kk++) {
            uint32_t ah[2][4];
            #pragma unroll
            for (int mt = 0; mt < 2; mt++) {
                const uint32_t ad = base
                    + (uint32_t)((wm * 32 + mt * 16 + (lane & 15)) * 144
                                 + (kk * 16 + ((lane >> 4) << 3)) * 2);
                LDSM4(ah[mt], ad);
            }
            #pragma unroll
            for (int ng = 0; ng < 4; ng++) {
                uint32_t bh[4];
                const uint32_t bd = base + TS
                    + (uint32_t)((wn * 64 + ng * 16 + (lane & 7) + ((lane >> 4) << 3)) * 144
                                 + (kk * 16 + (((lane >> 3) & 1) << 3)) * 2);
                LDSM4(bh, bd);
                #pragma unroll
                for (int mt = 0; mt < 2; mt++)
                    #pragma unroll
                    for (int hh = 0; hh < 2; hh++)
                        MMA_F16(acc[mt][ng * 2 + hh], ah[mt], bh[2 * hh], bh[2 * hh + 1]);
            }
        }
        __syncthreads();
    }

    #pragma unroll
    for (int mt = 0; mt < 2; mt++) {
        const int o0 = m0 + wm * 32 + mt * 16 + (lane >> 2);
        const float s0 = gam[o0] * rsqrtf(var[o0] + BN_EPS);
        const float c0 = bet[o0] - mu[o0] * s0;
        const int o1 = o0 + 8;
        const float s1 = gam[o1] * rsqrtf(var[o1] + BN_EPS);
        const float c1 = bet[o1] - mu[o1] * s1;
        #pragma unroll
        for (int j = 0; j < 8; j++) {
            const int n = n0 + wn * 64 + j * 8 + (lane & 3) * 2;
            float2 v0, v1;
            v0.x = fmaxf(fmaf(acc[mt][j][0], s0, c0), 0.0f);
            v0.y = fmaxf(fmaf(acc[mt][j][1], s0, c0), 0.0f);
            v1.x = fmaxf(fmaf(acc[mt][j][2], s1, c1), 0.0f);
            v1.y = fmaxf(fmaf(acc[mt][j][3], s1, c1), 0.0f);
            *(float2*)(outF + ((size_t)b * CO + o0) * NPTS + n) = v0;
            *(float2*)(outF + ((size_t)b * CO + o1) * NPTS + n) = v1;
        }
    }
}

// ---------------------------------------------------------------------------
extern "C" void kernel_launch(void* const* d_in, const int* in_sizes, int n_in,
                              void* d_out, int out_size)
{
    const float* target = (const float*)d_in[0];
    const float* source = (const float*)d_in[1];
    const float* tfeat  = (const float*)d_in[2];
    const float* sfeat  = (const float*)d_in[3];
    const float* w0     = (const float*)d_in[4];
    const float* g0     = (const float*)d_in[5];
    const float* b0     = (const float*)d_in[6];
    const float* mu0    = (const float*)d_in[7];
    const float* var0   = (const float*)d_in[8];
    const float* w1     = (const float*)d_in[9];
    const float* g1     = (const float*)d_in[10];
    const float* b1     = (const float*)d_in[11];
    const float* mu1    = (const float*)d_in[12];
    const float* var1   = (const float*)d_in[13];
    float* out = (float*)d_out;

    float*  Zt;  cudaGetSymbolAddress((void**)&Zt,  g_Zt);
    int4*   nni; cudaGetSymbolAddress((void**)&nni, g_nni);
    float4* nnw; cudaGetSymbolAddress((void**)&nnw, g_nnw);
    __half *W0, *W1, *T, *Y0;
    cudaGetSymbolAddress((void**)&W0, g_W0); cudaGetSymbolAddress((void**)&W1, g_W1);
    cudaGetSymbolAddress((void**)&T,  g_T);  cudaGetSymbolAddress((void**)&Y0, g_Y0);

    constexpr int SMEM_L0 = 256 * 272 + 128 * 272;   // 104448
    constexpr int SMEM_L1 = 2 * 2 * 128 * 144;       // 73728
    cudaFuncSetAttribute(mma_layer0_kernel,
                         cudaFuncAttributeMaxDynamicSharedMemorySize, SMEM_L0);
    cudaFuncSetAttribute(mma_layer1_kernel,
                         cudaFuncAttributeMaxDynamicSharedMemorySize, SMEM_L1);

    // 1) three_nn (2 points/thread)
    {
        dim3 grid(NPTS / 512, B_SZ);
        three_nn_kernel<<<grid, 256>>>(target, source, nni, nnw);
    }
    // 2) Zt = (w0[:, :256] @ sfeat)^T
    {
        dim3 grid(MSRC / 128, CO / 128, B_SZ);
        zt_kernel<<<grid, 256>>>(w0, sfeat, Zt);
    }
    // 3) weight converts (merged)
    conv_w2_kernel<<<(CO * C1 + CO * CO + 255) / 256, 256>>>(w0, w1, W0, W1);
    // 4) tfeat transpose -> fp16
    {
        dim3 grid(NPTS / 32, C1 / 32, B_SZ);
        tfeat_t_kernel<<<grid, 256>>>(tfeat, T);
    }
    // 5) layer 0 (wide tile, full-K resident) -> Y0^T fp16
    {
        dim3 grid(NPTS / 256, CO / 128, B_SZ);
        mma_layer0_kernel<<<grid, 512, SMEM_L0>>>(
            W0, T, Y0, g0, b0, mu0, var0, nni, nnw, Zt);
    }
    // 6) layer 1 -> out fp32
    {
        dim3 grid(NPTS / 128, CO / 128, B_SZ);
        mma_layer1_kernel<<<grid, 256, SMEM_L1>>>(
            W1, Y0, out, g1, b1, mu1, var1);
    }
    (void)in_sizes; (void)n_in; (void)out_size;
}

// round 15
// speedup vs baseline: 1.1790x; 1.1790x over previous
#include <cuda_runtime.h>
#include <cuda_fp16.h>
#include <cstdint>

#define B_SZ 8
#define NPTS 16384
#define MSRC 1024
#define C1   128
#define C2   256
#define CIN  384
#define CO   256
#define BN_EPS 1e-5f

// ---------------------------------------------------------------------------
// Scratch (allocation-free)
// ---------------------------------------------------------------------------
__device__ __align__(256) float  g_Zt [(size_t)B_SZ * MSRC * CO];
__device__ __align__(256) int4   g_nni[(size_t)B_SZ * NPTS];
__device__ __align__(256) float4 g_nnw[(size_t)B_SZ * NPTS];
__device__ __align__(256) __half g_W0 [CO * C1];
__device__ __align__(256) __half g_W1 [CO * CO];
__device__ __align__(256) __half g_T  [(size_t)B_SZ * NPTS * C1];   // tfeat^T fp16
__device__ __align__(256) __half g_Y0 [(size_t)B_SZ * NPTS * CO];   // Y0^T fp16

// ---------------------------------------------------------------------------
// PTX helpers (sm_100-safe)
// ---------------------------------------------------------------------------
__device__ __forceinline__ uint32_t smem_u32(const void* p) {
    uint32_t a;
    asm("{ .reg .u64 t; cvta.to.shared.u64 t, %1; cvt.u32.u64 %0, t; }" : "=r"(a) : "l"(p));
    return a;
}
#define CP16(dst, src) \
    asm volatile("cp.async.cg.shared.global [%0], [%1], 16;" :: "r"(dst), "l"(src))
#define CP_COMMIT() asm volatile("cp.async.commit_group;" ::: "memory")
#define CP_WAIT(n)  asm volatile("cp.async.wait_group %0;" :: "n"(n) : "memory")

#define LDSM4(r, addr) \
    asm volatile("ldmatrix.sync.aligned.m8n8.x4.shared.b16 {%0,%1,%2,%3}, [%4];" \
        : "=r"((r)[0]), "=r"((r)[1]), "=r"((r)[2]), "=r"((r)[3]) : "r"(addr))

#define MMA_F16(d, a, b0, b1) \
    asm volatile("mma.sync.aligned.m16n8k16.row.col.f32.f16.f16.f32 " \
        "{%0,%1,%2,%3}, {%4,%5,%6,%7}, {%8,%9}, {%0,%1,%2,%3};" \
        : "+f"((d)[0]), "+f"((d)[1]), "+f"((d)[2]), "+f"((d)[3]) \
        : "r"((a)[0]), "r"((a)[1]), "r"((a)[2]), "r"((a)[3]), "r"(b0), "r"(b1))

// ---------------------------------------------------------------------------
// three_nn: 2 target points per thread. Grid: (NPTS/512, B), 256 threads.
// ---------------------------------------------------------------------------
__global__ void __launch_bounds__(256)
three_nn_kernel(const float* __restrict__ target, const float* __restrict__ source,
                int4* __restrict__ nni, float4* __restrict__ nnw)
{
    const int b = blockIdx.y, t = threadIdx.x;
    const int ia = blockIdx.x * 512 + t;
    const int ib = ia + 256;
    __shared__ float4 s[MSRC];
    const float* src = source + (size_t)b * MSRC * 3;
    for (int j = t; j < MSRC; j += 256) {
        const float x = src[j * 3 + 0], y = src[j * 3 + 1], z = src[j * 3 + 2];
        s[j] = make_float4(x, y, z, x * x + y * y + z * z);
    }
    __syncthreads();

    const float* tpa = target + ((size_t)b * NPTS + ia) * 3;
    const float* tpb = target + ((size_t)b * NPTS + ib) * 3;
    const float pax = tpa[0], pay = tpa[1], paz = tpa[2];
    const float pbx = tpb[0], pby = tpb[1], pbz = tpb[2];
    const float qax = -2.0f * pax, qay = -2.0f * pay, qaz = -2.0f * paz;
    const float qbx = -2.0f * pbx, qby = -2.0f * pby, qbz = -2.0f * pbz;

    float a0 = 3.4e38f, a1 = 3.4e38f, a2 = 3.4e38f;
    float f0 = 3.4e38f, f1 = 3.4e38f, f2 = 3.4e38f;
    int   ja0 = 0, ja1 = 0, ja2 = 0, jb0 = 0, jb1 = 0, jb2 = 0;
    #pragma unroll 4
    for (int j = 0; j < MSRC; j++) {
        const float4 v = s[j];
        const float ea = fmaf(qax, v.x, fmaf(qay, v.y, fmaf(qaz, v.z, v.w)));
        const float eb = fmaf(qbx, v.x, fmaf(qby, v.y, fmaf(qbz, v.z, v.w)));
        if (ea < a0)      { a2 = a1; ja2 = ja1; a1 = a0; ja1 = ja0; a0 = ea; ja0 = j; }
        else if (ea < a1) { a2 = a1; ja2 = ja1; a1 = ea; ja1 = j; }
        else if (ea < a2) { a2 = ea; ja2 = j; }
        if (eb < f0)      { f2 = f1; jb2 = jb1; f1 = f0; jb1 = jb0; f0 = eb; jb0 = j; }
        else if (eb < f1) { f2 = f1; jb2 = jb1; f1 = eb; jb1 = j; }
        else if (eb < f2) { f2 = eb; jb2 = j; }
    }
    {
        float d[3]; const int jj[3] = {ja0, ja1, ja2};
        #pragma unroll
        for (int k = 0; k < 3; k++) {
            const float4 v = s[jj[k]];
            const float dx = pax - v.x, dy = pay - v.y, dz = paz - v.z;
            d[k] = dx * dx + dy * dy + dz * dz;
        }
        const float r0 = 1.0f / (d[0] + 1e-8f), r1 = 1.0f / (d[1] + 1e-8f), r2 = 1.0f / (d[2] + 1e-8f);
        const float rs = 1.0f / (r0 + r1 + r2);
        nni[(size_t)b * NPTS + ia] = make_int4(ja0, ja1, ja2, 0);
        nnw[(size_t)b * NPTS + ia] = make_float4(r0 * rs, r1 * rs, r2 * rs, 0.0f);
    }
    {
        float d[3]; const int jj[3] = {jb0, jb1, jb2};
        #pragma unroll
        for (int k = 0; k < 3; k++) {
            const float4 v = s[jj[k]];
            const float dx = pbx - v.x, dy = pby - v.y, dz = pbz - v.z;
            d[k] = dx * dx + dy * dy + dz * dz;
        }
        const float r0 = 1.0f / (d[0] + 1e-8f), r1 = 1.0f / (d[1] + 1e-8f), r2 = 1.0f / (d[2] + 1e-8f);
        const float rs = 1.0f / (r0 + r1 + r2);
        nni[(size_t)b * NPTS + ib] = make_int4(jb0, jb1, jb2, 0);
        nnw[(size_t)b * NPTS + ib] = make_float4(r0 * rs, r1 * rs, r2 * rs, 0.0f);
    }
}

// ---------------------------------------------------------------------------
// Zt = (w0[:, :256] @ sfeat)^T per batch (fp32 — keeps interp path exact)
// ---------------------------------------------------------------------------
__global__ void __launch_bounds__(256, 2)
zt_kernel(const float* __restrict__ w0, const float* __restrict__ sfeat, float* __restrict__ Zt)
{
    constexpr int BK = 16, TM = 8, TN = 8;
    __shared__ float Ss[BK][128];
    __shared__ float Ws[BK][128];
    const int b = blockIdx.z, J0 = blockIdx.x * 128, O0 = blockIdx.y * 128;
    const float* sf = sfeat + (size_t)b * C2 * MSRC;
    const int tid = threadIdx.x;
    const int rowO = tid >> 2, colK = (tid & 3) * 4;
    const int rowK = tid >> 5, colJ = (tid & 31) * 4;
    const int tj = (tid >> 4) * TM, to = (tid & 15) * TN;
    float acc[TM][TN];
    #pragma unroll
    for (int i = 0; i < TM; i++)
        #pragma unroll
        for (int j = 0; j < TN; j++) acc[i][j] = 0.0f;
    for (int k0 = 0; k0 < C2; k0 += BK) {
        #pragma unroll
        for (int p = 0; p < 2; p++) {
            const int r = rowO + p * 64;
            const float4 v = *(const float4*)(w0 + (size_t)(O0 + r) * CIN + k0 + colK);
            Ws[colK + 0][r] = v.x; Ws[colK + 1][r] = v.y;
            Ws[colK + 2][r] = v.z; Ws[colK + 3][r] = v.w;
        }
        #pragma unroll
        for (int p = 0; p < 2; p++) {
            const int r = rowK + p * 8;
            *(float4*)&Ss[r][colJ] = *(const float4*)(sf + (size_t)(k0 + r) * MSRC + J0 + colJ);
        }
        __syncthreads();
        #pragma unroll
        for (int kk = 0; kk < BK; kk++) {
            float a[TM], w[TN];
            #pragma unroll
            for (int i = 0; i < TM; i += 4) *(float4*)&a[i] = *(const float4*)&Ss[kk][tj + i];
            #pragma unroll
            for (int j = 0; j < TN; j += 4) *(float4*)&w[j] = *(const float4*)&Ws[kk][to + j];
            #pragma unroll
            for (int i = 0; i < TM; i++)
                #pragma unroll
                for (int j = 0; j < TN; j++) acc[i][j] = fmaf(a[i], w[j], acc[i][j]);
        }
        __syncthreads();
    }
    float* Zb = Zt + (size_t)b * MSRC * CO;
    #pragma unroll
    for (int i = 0; i < TM; i++)
        #pragma unroll
        for (int j = 0; j < TN; j += 4) {
            float4 v = make_float4(acc[i][j], acc[i][j+1], acc[i][j+2], acc[i][j+3]);
            *(float4*)(Zb + (size_t)(J0 + tj + i) * CO + O0 + to + j) = v;
        }
}

// ---------------------------------------------------------------------------
// Merged weight convert (W0 slice + W1, single fp16 planes)
// ---------------------------------------------------------------------------
__global__ void __launch_bounds__(256)
conv_w2_kernel(const float* __restrict__ w0, const float* __restrict__ w1,
               __half* __restrict__ W0, __half* __restrict__ W1)
{
    const int idx = blockIdx.x * 256 + threadIdx.x;
    if (idx < CO * C1) {
        const int o = idx / C1, k = idx % C1;
        W0[idx] = __float2half_rn(w0[(size_t)o * CIN + C2 + k]);
    } else {
        const int j = idx - CO * C1;
        if (j < CO * CO) {
            const int o = j / CO, k = j % CO;
            W1[j] = __float2half_rn(w1[(size_t)o * CO + k]);
        }
    }
}

// ---------------------------------------------------------------------------
// tfeat transpose: (B,C1,N) fp32 -> (B,N,C1) fp16
// ---------------------------------------------------------------------------
__global__ void __launch_bounds__(256)
tfeat_t_kernel(const float* __restrict__ tfeat, __half* __restrict__ T)
{
    __shared__ float sm[32][33];
    const int b = blockIdx.z;
    const int n0 = blockIdx.x * 32, c0 = blockIdx.y * 32;
    const int tx = threadIdx.x & 31, ty = threadIdx.x >> 5;
    const float* src = tfeat + (size_t)b * C1 * NPTS;
    #pragma unroll
    for (int i = 0; i < 4; i++) {
        const int c = ty + i * 8;
        sm[c][tx] = src[(size_t)(c0 + c) * NPTS + n0 + tx];
    }
    __syncthreads();
    #pragma unroll
    for (int i = 0; i < 4; i++) {
        const int n = ty + i * 8;
        T[((size_t)b * NPTS + n0 + n) * C1 + c0 + tx] = __float2half_rn(sm[tx][n]);
    }
}

// ---------------------------------------------------------------------------
// GEMM template (round-8 proven): fp16 single-pass, CTA 128m x 128n, BK=64,
// 8 warps (4m x 2n), cp.async double buffer, 2 CTAs/SM.
// L0GATHER: epilogue adds Zt gather + BN + ReLU -> Y0^T fp16.
// else:     BN + ReLU -> out fp32 (B, CO, N).
// ---------------------------------------------------------------------------
template<int KW, bool L0GATHER>
__global__ void __launch_bounds__(256, 2)
mma_layer_kernel(const __half* __restrict__ W, const __half* __restrict__ X,
                 float* __restrict__ outF, __half* __restrict__ outH,
                 const float* __restrict__ gam, const float* __restrict__ bet,
                 const float* __restrict__ mu,  const float* __restrict__ var,
                 const int4* __restrict__ nni, const float4* __restrict__ nnw,
                 const float* __restrict__ Zt)
{
    constexpr int KC  = KW / 64;
    constexpr int TS  = 128 * 144;
    constexpr int BUF = 2 * TS;
    extern __shared__ __align__(16) char smem[];
    const uint32_t sb = smem_u32(smem);

    const int tid = threadIdx.x, lane = tid & 31, wid = tid >> 5;
    const int wm = wid >> 1, wn = wid & 1;
    const int b = blockIdx.z, n0 = blockIdx.x * 128, m0 = blockIdx.y * 128;

    const __half* A_g = W + (size_t)m0 * KW;
    const __half* B_g = X + ((size_t)b * NPTS + n0) * KW;

    const int lr = tid >> 3;
    const int lc = (tid & 7) * 8;

    float acc[2][8][4];
    #pragma unroll
    for (int i = 0; i < 2; i++)
        #pragma unroll
        for (int j = 0; j < 8; j++)
            #pragma unroll
            for (int q = 0; q < 4; q++) acc[i][j][q] = 0.0f;

    #pragma unroll
    for (int it = 0; it < 4; it++) {
        const int r = lr + it * 32;
        const uint32_t so = (uint32_t)(r * 144 + lc * 2);
        CP16(sb + so,      A_g + (size_t)r * KW + lc);
        CP16(sb + TS + so, B_g + (size_t)r * KW + lc);
    }
    CP_COMMIT();

    for (int c = 0; c < KC; c++) {
        if (c + 1 < KC) {
            const int k0 = (c + 1) * 64;
            const uint32_t bufo = (uint32_t)(((c + 1) & 1) * BUF);
            #pragma unroll
            for (int it = 0; it < 4; it++) {
                const int r = lr + it * 32;
                const uint32_t so = bufo + (uint32_t)(r * 144 + lc * 2);
                CP16(sb + so,      A_g + (size_t)r * KW + k0 + lc);
                CP16(sb + TS + so, B_g + (size_t)r * KW + k0 + lc);
            }
            CP_COMMIT();
            CP_WAIT(1);
        } else {
            CP_WAIT(0);
        }
        __syncthreads();

        const uint32_t base = sb + (uint32_t)((c & 1) * BUF);
        #pragma unroll
        for (int kk = 0; kk < 4; kk++) {
            uint32_t ah[2][4];
            #pragma unroll
            for (int mt = 0; mt < 2; mt++) {
                const uint32_t ad = base
                    + (uint32_t)((wm * 32 + mt * 16 + (lane & 15)) * 144
                                 + (kk * 16 + ((lane >> 4) << 3)) * 2);
                LDSM4(ah[mt], ad);
            }
            #pragma unroll
            for (int ng = 0; ng < 4; ng++) {
                uint32_t bh[4];
                const uint32_t bd = base + TS
                    + (uint32_t)((wn * 64 + ng * 16 + (lane & 7) + ((lane >> 4) << 3)) * 144
                                 + (kk * 16 + (((lane >> 3) & 1) << 3)) * 2);
                LDSM4(bh, bd);
                #pragma unroll
                for (int mt = 0; mt < 2; mt++)
                    #pragma unroll
                    for (int hh = 0; hh < 2; hh++)
                        MMA_F16(acc[mt][ng * 2 + hh], ah[mt], bh[2 * hh], bh[2 * hh + 1]);
            }
        }
        __syncthreads();
    }

    if (!L0GATHER) {
        #pragma unroll
        for (int mt = 0; mt < 2; mt++) {
            const int o0 = m0 + wm * 32 + mt * 16 + (lane >> 2);
            const float s0 = gam[o0] * rsqrtf(var[o0] + BN_EPS);
            const float c0 = bet[o0] - mu[o0] * s0;
            const int o1 = o0 + 8;
            const float s1 = gam[o1] * rsqrtf(var[o1] + BN_EPS);
            const float c1 = bet[o1] - mu[o1] * s1;
            #pragma unroll
            for (int j = 0; j < 8; j++) {
                const int n = n0 + wn * 64 + j * 8 + (lane & 3) * 2;
                float2 v0, v1;
                v0.x = fmaxf(fmaf(acc[mt][j][0], s0, c0), 0.0f);
                v0.y = fmaxf(fmaf(acc[mt][j][1], s0, c0), 0.0f);
                v1.x = fmaxf(fmaf(acc[mt][j][2], s1, c1), 0.0f);
                v1.y = fmaxf(fmaf(acc[mt][j][3], s1, c1), 0.0f);
                *(float2*)(outF + ((size_t)b * CO + o0) * NPTS + n) = v0;
                *(float2*)(outF + ((size_t)b * CO + o1) * NPTS + n) = v1;
            }
        }
    } else {
        float* S = (float*)smem;   // 128 x 132 fp32 = 67584 <= 73728
        #pragma unroll
        for (int mt = 0; mt < 2; mt++) {
            const int ol = wm * 32 + mt * 16 + (lane >> 2);
            #pragma unroll
            for (int j = 0; j < 8; j++) {
                const int nl = wn * 64 + j * 8 + (lane & 3) * 2;
                S[(nl + 0) * 132 + ol]     = acc[mt][j][0];
                S[(nl + 1) * 132 + ol]     = acc[mt][j][1];
                S[(nl + 0) * 132 + ol + 8] = acc[mt][j][2];
                S[(nl + 1) * 132 + ol + 8] = acc[mt][j][3];
            }
        }
        __syncthreads();

        const size_t bn = (size_t)b * NPTS;
        const float* Zb = Zt + (size_t)b * MSRC * CO;
        #pragma unroll 2
        for (int it = 0; it < 16; it++) {
            const int item = tid + it * 256;
            const int nl = item >> 5, o4 = (item & 31) * 4;
            const int n = n0 + nl, o = m0 + o4;
            float4 v = *(float4*)(S + nl * 132 + o4);
            const int4   ji = nni[bn + n];
            const float4 jw = nnw[bn + n];
            const float4 z0 = *(const float4*)(Zb + (size_t)ji.x * CO + o);
            const float4 z1 = *(const float4*)(Zb + (size_t)ji.y * CO + o);
            const float4 z2 = *(const float4*)(Zb + (size_t)ji.z * CO + o);
            v.x += jw.x * z0.x + jw.y * z1.x + jw.z * z2.x;
            v.y += jw.x * z0.y + jw.y * z1.y + jw.z * z2.y;
            v.z += jw.x * z0.z + jw.y * z1.z + jw.z * z2.z;
            v.w += jw.x * z0.w + jw.y * z1.w + jw.z * z2.w;
            const float4 g4 = *(const float4*)(gam + o);
            const float4 b4 = *(const float4*)(bet + o);
            const float4 m4 = *(const float4*)(mu  + o);
            const float4 q4 = *(const float4*)(var + o);
            const float sx = g4.x * rsqrtf(q4.x + BN_EPS);
            const float sy = g4.y * rsqrtf(q4.y + BN_EPS);
            const float sz = g4.z * rsqrtf(q4.z + BN_EPS);
            const float sw = g4.w * rsqrtf(q4.w + BN_EPS);
            union { __half h[4]; uint2 u; } H;
            H.h[0] = __float2half_rn(fmaxf(fmaf(v.x, sx, b4.x - m4.x * sx), 0.0f));
            H.h[1] = __float2half_rn(fmaxf(fmaf(v.y, sy, b4.y - m4.y * sy), 0.0f));
            H.h[2] = __float2half_rn(fmaxf(fmaf(v.z, sz, b4.z - m4.z * sz), 0.0f));
            H.h[3] = __float2half_rn(fmaxf(fmaf(v.w, sw, b4.w - m4.w * sw), 0.0f));
            *(uint2*)(outH + (bn + n) * CO + o) = H.u;
        }
    }
}

// ---------------------------------------------------------------------------
extern "C" void kernel_launch(void* const* d_in, const int* in_sizes, int n_in,
                              void* d_out, int out_size)
{
    const float* target = (const float*)d_in[0];
    const float* source = (const float*)d_in[1];
    const float* tfeat  = (const float*)d_in[2];
    const float* sfeat  = (const float*)d_in[3];
    const float* w0     = (const float*)d_in[4];
    const float* g0     = (const float*)d_in[5];
    const float* b0     = (const float*)d_in[6];
    const float* mu0    = (const float*)d_in[7];
    const float* var0   = (const float*)d_in[8];
    const float* w1     = (const float*)d_in[9];
    const float* g1     = (const float*)d_in[10];
    const float* b1     = (const float*)d_in[11];
    const float* mu1    = (const float*)d_in[12];
    const float* var1   = (const float*)d_in[13];
    float* out = (float*)d_out;

    float*  Zt;  cudaGetSymbolAddress((void**)&Zt,  g_Zt);
    int4*   nni; cudaGetSymbolAddress((void**)&nni, g_nni);
    float4* nnw; cudaGetSymbolAddress((void**)&nnw, g_nnw);
    __half *W0, *W1, *T, *Y0;
    cudaGetSymbolAddress((void**)&W0, g_W0); cudaGetSymbolAddress((void**)&W1, g_W1);
    cudaGetSymbolAddress((void**)&T,  g_T);  cudaGetSymbolAddress((void**)&Y0, g_Y0);

    constexpr int SMEM_MMA = 2 * 2 * 128 * 144;  // 73728
    cudaFuncSetAttribute(mma_layer_kernel<C1, true>,
                         cudaFuncAttributeMaxDynamicSharedMemorySize, SMEM_MMA);
    cudaFuncSetAttribute(mma_layer_kernel<CO, false>,
                         cudaFuncAttributeMaxDynamicSharedMemorySize, SMEM_MMA);

    // 1) three_nn (2 points/thread)
    {
        dim3 grid(NPTS / 512, B_SZ);
        three_nn_kernel<<<grid, 256>>>(target, source, nni, nnw);
    }
    // 2) Zt = (w0[:, :256] @ sfeat)^T
    {
        dim3 grid(MSRC / 128, CO / 128, B_SZ);
        zt_kernel<<<grid, 256>>>(w0, sfeat, Zt);
    }
    // 3) weight converts (merged)
    conv_w2_kernel<<<(CO * C1 + CO * CO + 255) / 256, 256>>>(w0, w1, W0, W1);
    // 4) tfeat transpose -> fp16
    {
        dim3 grid(NPTS / 32, C1 / 32, B_SZ);
        tfeat_t_kernel<<<grid, 256>>>(tfeat, T);
    }
    // 5) layer 0: W0 @ T^T + gather(Zt) + BN + ReLU -> Y0^T fp16
    {
        dim3 grid(NPTS / 128, CO / 128, B_SZ);
        mma_layer_kernel<C1, true><<<grid, 256, SMEM_MMA>>>(
            W0, T, nullptr, Y0, g0, b0, mu0, var0, nni, nnw, Zt);
    }
    // 6) layer 1: W1 @ Y0^T + BN + ReLU -> out fp32 (B, CO, N)
    {
        dim3 grid(NPTS / 128, CO / 128, B_SZ);
        mma_layer_kernel<CO, false><<<grid, 256, SMEM_MMA>>>(
            W1, Y0, out, nullptr, g1, b1, mu1, var1, nullptr, nullptr, nullptr);
    }
    (void)in_sizes; (void)n_in; (void)out_size;
}

// round 16
// speedup vs baseline: 1.2657x; 1.0735x over previous
#include <cuda_runtime.h>
#include <cuda_fp16.h>
#include <cstdint>

#define B_SZ 8
#define NPTS 16384
#define MSRC 1024
#define C1   128
#define C2   256
#define CIN  384
#define CO   256
#define BN_EPS 1e-5f

// ---------------------------------------------------------------------------
// Scratch (allocation-free)
// ---------------------------------------------------------------------------
__device__ __align__(256) float  g_Zt [(size_t)B_SZ * MSRC * CO];
__device__ __align__(256) int4   g_nni[(size_t)B_SZ * NPTS];
__device__ __align__(256) float4 g_nnw[(size_t)B_SZ * NPTS];
__device__ __align__(256) __half g_W0 [CO * C1];
__device__ __align__(256) __half g_W1 [CO * CO];
__device__ __align__(256) __half g_T  [(size_t)B_SZ * NPTS * C1];   // tfeat^T fp16
__device__ __align__(256) __half g_Y0 [(size_t)B_SZ * NPTS * CO];   // Y0^T fp16

// ---------------------------------------------------------------------------
// PTX helpers (sm_100-safe)
// ---------------------------------------------------------------------------
__device__ __forceinline__ uint32_t smem_u32(const void* p) {
    uint32_t a;
    asm("{ .reg .u64 t; cvta.to.shared.u64 t, %1; cvt.u32.u64 %0, t; }" : "=r"(a) : "l"(p));
    return a;
}
#define CP16(dst, src) \
    asm volatile("cp.async.cg.shared.global [%0], [%1], 16;" :: "r"(dst), "l"(src))
#define CP_COMMIT() asm volatile("cp.async.commit_group;" ::: "memory")
#define CP_WAIT(n)  asm volatile("cp.async.wait_group %0;" :: "n"(n) : "memory")

#define LDSM4(r, addr) \
    asm volatile("ldmatrix.sync.aligned.m8n8.x4.shared.b16 {%0,%1,%2,%3}, [%4];" \
        : "=r"((r)[0]), "=r"((r)[1]), "=r"((r)[2]), "=r"((r)[3]) : "r"(addr))

#define MMA_F16(d, a, b0, b1) \
    asm volatile("mma.sync.aligned.m16n8k16.row.col.f32.f16.f16.f32 " \
        "{%0,%1,%2,%3}, {%4,%5,%6,%7}, {%8,%9}, {%0,%1,%2,%3};" \
        : "+f"((d)[0]), "+f"((d)[1]), "+f"((d)[2]), "+f"((d)[3]) \
        : "r"((a)[0]), "r"((a)[1]), "r"((a)[2]), "r"((a)[3]), "r"(b0), "r"(b1))

// ---------------------------------------------------------------------------
// three_nn: 2 target points per thread. Grid: (NPTS/512, B), 256 threads.
// ---------------------------------------------------------------------------
__global__ void __launch_bounds__(256)
three_nn_kernel(const float* __restrict__ target, const float* __restrict__ source,
                int4* __restrict__ nni, float4* __restrict__ nnw)
{
    const int b = blockIdx.y, t = threadIdx.x;
    const int ia = blockIdx.x * 512 + t;
    const int ib = ia + 256;
    __shared__ float4 s[MSRC];
    const float* src = source + (size_t)b * MSRC * 3;
    for (int j = t; j < MSRC; j += 256) {
        const float x = src[j * 3 + 0], y = src[j * 3 + 1], z = src[j * 3 + 2];
        s[j] = make_float4(x, y, z, x * x + y * y + z * z);
    }
    __syncthreads();

    const float* tpa = target + ((size_t)b * NPTS + ia) * 3;
    const float* tpb = target + ((size_t)b * NPTS + ib) * 3;
    const float pax = tpa[0], pay = tpa[1], paz = tpa[2];
    const float pbx = tpb[0], pby = tpb[1], pbz = tpb[2];
    const float qax = -2.0f * pax, qay = -2.0f * pay, qaz = -2.0f * paz;
    const float qbx = -2.0f * pbx, qby = -2.0f * pby, qbz = -2.0f * pbz;

    float a0 = 3.4e38f, a1 = 3.4e38f, a2 = 3.4e38f;
    float f0 = 3.4e38f, f1 = 3.4e38f, f2 = 3.4e38f;
    int   ja0 = 0, ja1 = 0, ja2 = 0, jb0 = 0, jb1 = 0, jb2 = 0;
    #pragma unroll 4
    for (int j = 0; j < MSRC; j++) {
        const float4 v = s[j];
        const float ea = fmaf(qax, v.x, fmaf(qay, v.y, fmaf(qaz, v.z, v.w)));
        const float eb = fmaf(qbx, v.x, fmaf(qby, v.y, fmaf(qbz, v.z, v.w)));
        if (ea < a0)      { a2 = a1; ja2 = ja1; a1 = a0; ja1 = ja0; a0 = ea; ja0 = j; }
        else if (ea < a1) { a2 = a1; ja2 = ja1; a1 = ea; ja1 = j; }
        else if (ea < a2) { a2 = ea; ja2 = j; }
        if (eb < f0)      { f2 = f1; jb2 = jb1; f1 = f0; jb1 = jb0; f0 = eb; jb0 = j; }
        else if (eb < f1) { f2 = f1; jb2 = jb1; f1 = eb; jb1 = j; }
        else if (eb < f2) { f2 = eb; jb2 = j; }
    }
    {
        float d[3]; const int jj[3] = {ja0, ja1, ja2};
        #pragma unroll
        for (int k = 0; k < 3; k++) {
            const float4 v = s[jj[k]];
            const float dx = pax - v.x, dy = pay - v.y, dz = paz - v.z;
            d[k] = dx * dx + dy * dy + dz * dz;
        }
        const float r0 = 1.0f / (d[0] + 1e-8f), r1 = 1.0f / (d[1] + 1e-8f), r2 = 1.0f / (d[2] + 1e-8f);
        const float rs = 1.0f / (r0 + r1 + r2);
        nni[(size_t)b * NPTS + ia] = make_int4(ja0, ja1, ja2, 0);
        nnw[(size_t)b * NPTS + ia] = make_float4(r0 * rs, r1 * rs, r2 * rs, 0.0f);
    }
    {
        float d[3]; const int jj[3] = {jb0, jb1, jb2};
        #pragma unroll
        for (int k = 0; k < 3; k++) {
            const float4 v = s[jj[k]];
            const float dx = pbx - v.x, dy = pby - v.y, dz = pbz - v.z;
            d[k] = dx * dx + dy * dy + dz * dz;
        }
        const float r0 = 1.0f / (d[0] + 1e-8f), r1 = 1.0f / (d[1] + 1e-8f), r2 = 1.0f / (d[2] + 1e-8f);
        const float rs = 1.0f / (r0 + r1 + r2);
        nni[(size_t)b * NPTS + ib] = make_int4(jb0, jb1, jb2, 0);
        nnw[(size_t)b * NPTS + ib] = make_float4(r0 * rs, r1 * rs, r2 * rs, 0.0f);
    }
}

// ---------------------------------------------------------------------------
// Zt = (w0[:, :256] @ sfeat)^T per batch (fp32 — keeps interp path exact)
// ---------------------------------------------------------------------------
__global__ void __launch_bounds__(256, 2)
zt_kernel(const float* __restrict__ w0, const float* __restrict__ sfeat, float* __restrict__ Zt)
{
    constexpr int BK = 16, TM = 8, TN = 8;
    __shared__ float Ss[BK][128];
    __shared__ float Ws[BK][128];
    const int b = blockIdx.z, J0 = blockIdx.x * 128, O0 = blockIdx.y * 128;
    const float* sf = sfeat + (size_t)b * C2 * MSRC;
    const int tid = threadIdx.x;
    const int rowO = tid >> 2, colK = (tid & 3) * 4;
    const int rowK = tid >> 5, colJ = (tid & 31) * 4;
    const int tj = (tid >> 4) * TM, to = (tid & 15) * TN;
    float acc[TM][TN];
    #pragma unroll
    for (int i = 0; i < TM; i++)
        #pragma unroll
        for (int j = 0; j < TN; j++) acc[i][j] = 0.0f;
    for (int k0 = 0; k0 < C2; k0 += BK) {
        #pragma unroll
        for (int p = 0; p < 2; p++) {
            const int r = rowO + p * 64;
            const float4 v = *(const float4*)(w0 + (size_t)(O0 + r) * CIN + k0 + colK);
            Ws[colK + 0][r] = v.x; Ws[colK + 1][r] = v.y;
            Ws[colK + 2][r] = v.z; Ws[colK + 3][r] = v.w;
        }
        #pragma unroll
        for (int p = 0; p < 2; p++) {
            const int r = rowK + p * 8;
            *(float4*)&Ss[r][colJ] = *(const float4*)(sf + (size_t)(k0 + r) * MSRC + J0 + colJ);
        }
        __syncthreads();
        #pragma unroll
        for (int kk = 0; kk < BK; kk++) {
            float a[TM], w[TN];
            #pragma unroll
            for (int i = 0; i < TM; i += 4) *(float4*)&a[i] = *(const float4*)&Ss[kk][tj + i];
            #pragma unroll
            for (int j = 0; j < TN; j += 4) *(float4*)&w[j] = *(const float4*)&Ws[kk][to + j];
            #pragma unroll
            for (int i = 0; i < TM; i++)
                #pragma unroll
                for (int j = 0; j < TN; j++) acc[i][j] = fmaf(a[i], w[j], acc[i][j]);
        }
        __syncthreads();
    }
    float* Zb = Zt + (size_t)b * MSRC * CO;
    #pragma unroll
    for (int i = 0; i < TM; i++)
        #pragma unroll
        for (int j = 0; j < TN; j += 4) {
            float4 v = make_float4(acc[i][j], acc[i][j+1], acc[i][j+2], acc[i][j+3]);
            *(float4*)(Zb + (size_t)(J0 + tj + i) * CO + O0 + to + j) = v;
        }
}

// ---------------------------------------------------------------------------
// Merged weight convert (W0 slice + W1, single fp16 planes)
// ---------------------------------------------------------------------------
__global__ void __launch_bounds__(256)
conv_w2_kernel(const float* __restrict__ w0, const float* __restrict__ w1,
               __half* __restrict__ W0, __half* __restrict__ W1)
{
    const int idx = blockIdx.x * 256 + threadIdx.x;
    if (idx < CO * C1) {
        const int o = idx / C1, k = idx % C1;
        W0[idx] = __float2half_rn(w0[(size_t)o * CIN + C2 + k]);
    } else {
        const int j = idx - CO * C1;
        if (j < CO * CO) {
            const int o = j / CO, k = j % CO;
            W1[j] = __float2half_rn(w1[(size_t)o * CO + k]);
        }
    }
}

// ---------------------------------------------------------------------------
// tfeat transpose: (B,C1,N) fp32 -> (B,N,C1) fp16
// ---------------------------------------------------------------------------
__global__ void __launch_bounds__(256)
tfeat_t_kernel(const float* __restrict__ tfeat, __half* __restrict__ T)
{
    __shared__ float sm[32][33];
    const int b = blockIdx.z;
    const int n0 = blockIdx.x * 32, c0 = blockIdx.y * 32;
    const int tx = threadIdx.x & 31, ty = threadIdx.x >> 5;
    const float* src = tfeat + (size_t)b * C1 * NPTS;
    #pragma unroll
    for (int i = 0; i < 4; i++) {
        const int c = ty + i * 8;
        sm[c][tx] = src[(size_t)(c0 + c) * NPTS + n0 + tx];
    }
    __syncthreads();
    #pragma unroll
    for (int i = 0; i < 4; i++) {
        const int n = ty + i * 8;
        T[((size_t)b * NPTS + n0 + n) * C1 + c0 + tx] = __float2half_rn(sm[tx][n]);
    }
}

// ---------------------------------------------------------------------------
// GEMM template: fp16 single-pass, CTA 128m x 128n, BK=64, 8 warps (4m x 2n),
// cp.async double buffer, 2 CTAs/SM.
// L0GATHER: nni/nnw staged into smem via cp.async during the mainloop, BN
// scale/bias precomputed once into smem; epilogue gather + BN + ReLU -> Y0^T.
// else: BN + ReLU -> out fp32 (B, CO, N).
// ---------------------------------------------------------------------------
template<int KW, bool L0GATHER>
__global__ void __launch_bounds__(256, 2)
mma_layer_kernel(const __half* __restrict__ W, const __half* __restrict__ X,
                 float* __restrict__ outF, __half* __restrict__ outH,
                 const float* __restrict__ gam, const float* __restrict__ bet,
                 const float* __restrict__ mu,  const float* __restrict__ var,
                 const int4* __restrict__ nni, const float4* __restrict__ nnw,
                 const float* __restrict__ Zt)
{
    constexpr int KC    = KW / 64;
    constexpr int TS    = 128 * 144;
    constexpr int BUF   = 2 * TS;
    constexpr int STAGE = 2 * BUF;          // 73728: staging area (L0 only)
    extern __shared__ __align__(16) char smem[];
    const uint32_t sb = smem_u32(smem);

    const int tid = threadIdx.x, lane = tid & 31, wid = tid >> 5;
    const int wm = wid >> 1, wn = wid & 1;
    const int b = blockIdx.z, n0 = blockIdx.x * 128, m0 = blockIdx.y * 128;
    const size_t bn = (size_t)b * NPTS;

    const __half* A_g = W + (size_t)m0 * KW;
    const __half* B_g = X + (bn + n0) * KW;

    const int lr = tid >> 3;
    const int lc = (tid & 7) * 8;

    float acc[2][8][4];
    #pragma unroll
    for (int i = 0; i < 2; i++)
        #pragma unroll
        for (int j = 0; j < 8; j++)
            #pragma unroll
            for (int q = 0; q < 4; q++) acc[i][j][q] = 0.0f;

    #pragma unroll
    for (int it = 0; it < 4; it++) {
        const int r = lr + it * 32;
        const uint32_t so = (uint32_t)(r * 144 + lc * 2);
        CP16(sb + so,      A_g + (size_t)r * KW + lc);
        CP16(sb + TS + so, B_g + (size_t)r * KW + lc);
    }
    if (L0GATHER && tid < 128) {
        // stage nni/nnw for this CTA's 128 points (same group as chunk 0 —
        // guaranteed complete before the epilogue's first access)
        CP16(sb + STAGE + tid * 16,        nni + bn + n0 + tid);
        CP16(sb + STAGE + 2048 + tid * 16, nnw + bn + n0 + tid);
    }
    CP_COMMIT();

    if (L0GATHER && tid < 128) {
        // precompute BN (scale, bias) per channel; visible after first sync
        const int o = m0 + tid;
        const float s = gam[o] * rsqrtf(var[o] + BN_EPS);
        ((float2*)(smem + STAGE + 4096))[tid] = make_float2(s, bet[o] - mu[o] * s);
    }

    for (int c = 0; c < KC; c++) {
        if (c + 1 < KC) {
            const int k0 = (c + 1) * 64;
            const uint32_t bufo = (uint32_t)(((c + 1) & 1) * BUF);
            #pragma unroll
            for (int it = 0; it < 4; it++) {
                const int r = lr + it * 32;
                const uint32_t so = bufo + (uint32_t)(r * 144 + lc * 2);
                CP16(sb + so,      A_g + (size_t)r * KW + k0 + lc);
                CP16(sb + TS + so, B_g + (size_t)r * KW + k0 + lc);
            }
            CP_COMMIT();
            CP_WAIT(1);
        } else {
            CP_WAIT(0);
        }
        __syncthreads();

        const uint32_t base = sb + (uint32_t)((c & 1) * BUF);
        #pragma unroll
        for (int kk = 0; kk < 4; kk++) {
            uint32_t ah[2][4];
            #pragma unroll
            for (int mt = 0; mt < 2; mt++) {
                const uint32_t ad = base
                    + (uint32_t)((wm * 32 + mt * 16 + (lane & 15)) * 144
                                 + (kk * 16 + ((lane >> 4) << 3)) * 2);
                LDSM4(ah[mt], ad);
            }
            #pragma unroll
            for (int ng = 0; ng < 4; ng++) {
                uint32_t bh[4];
                const uint32_t bd = base + TS
                    + (uint32_t)((wn * 64 + ng * 16 + (lane & 7) + ((lane >> 4) << 3)) * 144
                                 + (kk * 16 + (((lane >> 3) & 1) << 3)) * 2);
                LDSM4(bh, bd);
                #pragma unroll
                for (int mt = 0; mt < 2; mt++)
                    #pragma unroll
                    for (int hh = 0; hh < 2; hh++)
                        MMA_F16(acc[mt][ng * 2 + hh], ah[mt], bh[2 * hh], bh[2 * hh + 1]);
            }
        }
        __syncthreads();
    }

    if (!L0GATHER) {
        #pragma unroll
        for (int mt = 0; mt < 2; mt++) {
            const int o0 = m0 + wm * 32 + mt * 16 + (lane >> 2);
            const float s0 = gam[o0] * rsqrtf(var[o0] + BN_EPS);
            const float c0 = bet[o0] - mu[o0] * s0;
            const int o1 = o0 + 8;
            const float s1 = gam[o1] * rsqrtf(var[o1] + BN_EPS);
            const float c1 = bet[o1] - mu[o1] * s1;
            #pragma unroll
            for (int j = 0; j < 8; j++) {
                const int n = n0 + wn * 64 + j * 8 + (lane & 3) * 2;
                float2 v0, v1;
                v0.x = fmaxf(fmaf(acc[mt][j][0], s0, c0), 0.0f);
                v0.y = fmaxf(fmaf(acc[mt][j][1], s0, c0), 0.0f);
                v1.x = fmaxf(fmaf(acc[mt][j][2], s1, c1), 0.0f);
                v1.y = fmaxf(fmaf(acc[mt][j][3], s1, c1), 0.0f);
                *(float2*)(outF + ((size_t)b * CO + o0) * NPTS + n) = v0;
                *(float2*)(outF + ((size_t)b * CO + o1) * NPTS + n) = v1;
            }
        }
    } else {
        float* S = (float*)smem;   // 128 x 132 fp32 = 67584 < 73728 (staging safe)
        #pragma unroll
        for (int mt = 0; mt < 2; mt++) {
            const int ol = wm * 32 + mt * 16 + (lane >> 2);
            #pragma unroll
            for (int j = 0; j < 8; j++) {
                const int nl = wn * 64 + j * 8 + (lane & 3) * 2;
                S[(nl + 0) * 132 + ol]     = acc[mt][j][0];
                S[(nl + 1) * 132 + ol]     = acc[mt][j][1];
                S[(nl + 0) * 132 + ol + 8] = acc[mt][j][2];
                S[(nl + 1) * 132 + ol + 8] = acc[mt][j][3];
            }
        }
        __syncthreads();

        const int4*   s_ji = (const int4*)(smem + STAGE);
        const float4* s_jw = (const float4*)(smem + STAGE + 2048);
        const float*  s_bn = (const float*)(smem + STAGE + 4096);   // (s,c) pairs
        const float* Zb = Zt + (size_t)b * MSRC * CO;
        #pragma unroll 4
        for (int it = 0; it < 16; it++) {
            const int item = tid + it * 256;
            const int nl = item >> 5, o4 = (item & 31) * 4;
            const int n = n0 + nl, o = m0 + o4;
            const int4   ji = s_ji[nl];
            const float4 jw = s_jw[nl];
            const float4 z0 = *(const float4*)(Zb + (size_t)ji.x * CO + o);
            const float4 z1 = *(const float4*)(Zb + (size_t)ji.y * CO + o);
            const float4 z2 = *(const float4*)(Zb + (size_t)ji.z * CO + o);
            float4 v = *(float4*)(S + nl * 132 + o4);
            v.x += jw.x * z0.x + jw.y * z1.x + jw.z * z2.x;
            v.y += jw.x * z0.y + jw.y * z1.y + jw.z * z2.y;
            v.z += jw.x * z0.z + jw.y * z1.z + jw.z * z2.z;
            v.w += jw.x * z0.w + jw.y * z1.w + jw.z * z2.w;
            const float4 p0 = *(const float4*)(s_bn + o4 * 2);       // s0,c0,s1,c1
            const float4 p1 = *(const float4*)(s_bn + o4 * 2 + 4);   // s2,c2,s3,c3
            union { __half h[4]; uint2 u; } H;
            H.h[0] = __float2half_rn(fmaxf(fmaf(v.x, p0.x, p0.y), 0.0f));
            H.h[1] = __float2half_rn(fmaxf(fmaf(v.y, p0.z, p0.w), 0.0f));
            H.h[2] = __float2half_rn(fmaxf(fmaf(v.z, p1.x, p1.y), 0.0f));
            H.h[3] = __float2half_rn(fmaxf(fmaf(v.w, p1.z, p1.w), 0.0f));
            *(uint2*)(outH + (bn + n) * CO + o) = H.u;
        }
    }
}

// ---------------------------------------------------------------------------
extern "C" void kernel_launch(void* const* d_in, const int* in_sizes, int n_in,
                              void* d_out, int out_size)
{
    const float* target = (const float*)d_in[0];
    const float* source = (const float*)d_in[1];
    const float* tfeat  = (const float*)d_in[2];
    const float* sfeat  = (const float*)d_in[3];
    const float* w0     = (const float*)d_in[4];
    const float* g0     = (const float*)d_in[5];
    const float* b0     = (const float*)d_in[6];
    const float* mu0    = (const float*)d_in[7];
    const float* var0   = (const float*)d_in[8];
    const float* w1     = (const float*)d_in[9];
    const float* g1     = (const float*)d_in[10];
    const float* b1     = (const float*)d_in[11];
    const float* mu1    = (const float*)d_in[12];
    const float* var1   = (const float*)d_in[13];
    float* out = (float*)d_out;

    float*  Zt;  cudaGetSymbolAddress((void**)&Zt,  g_Zt);
    int4*   nni; cudaGetSymbolAddress((void**)&nni, g_nni);
    float4* nnw; cudaGetSymbolAddress((void**)&nnw, g_nnw);
    __half *W0, *W1, *T, *Y0;
    cudaGetSymbolAddress((void**)&W0, g_W0); cudaGetSymbolAddress((void**)&W1, g_W1);
    cudaGetSymbolAddress((void**)&T,  g_T);  cudaGetSymbolAddress((void**)&Y0, g_Y0);

    constexpr int SMEM_L1 = 2 * 2 * 128 * 144;        // 73728
    constexpr int SMEM_L0 = SMEM_L1 + 4096 + 1024;    // + nni/nnw + BN stage
    cudaFuncSetAttribute(mma_layer_kernel<C1, true>,
                         cudaFuncAttributeMaxDynamicSharedMemorySize, SMEM_L0);
    cudaFuncSetAttribute(mma_layer_kernel<CO, false>,
                         cudaFuncAttributeMaxDynamicSharedMemorySize, SMEM_L1);

    // 1) three_nn (2 points/thread)
    {
        dim3 grid(NPTS / 512, B_SZ);
        three_nn_kernel<<<grid, 256>>>(target, source, nni, nnw);
    }
    // 2) Zt = (w0[:, :256] @ sfeat)^T
    {
        dim3 grid(MSRC / 128, CO / 128, B_SZ);
        zt_kernel<<<grid, 256>>>(w0, sfeat, Zt);
    }
    // 3) weight converts (merged)
    conv_w2_kernel<<<(CO * C1 + CO * CO + 255) / 256, 256>>>(w0, w1, W0, W1);
    // 4) tfeat transpose -> fp16
    {
        dim3 grid(NPTS / 32, C1 / 32, B_SZ);
        tfeat_t_kernel<<<grid, 256>>>(tfeat, T);
    }
    // 5) layer 0: W0 @ T^T + gather(Zt) + BN + ReLU -> Y0^T fp16
    {
        dim3 grid(NPTS / 128, CO / 128, B_SZ);
        mma_layer_kernel<C1, true><<<grid, 256, SMEM_L0>>>(
            W0, T, nullptr, Y0, g0, b0, mu0, var0, nni, nnw, Zt);
    }
    // 6) layer 1: W1 @ Y0^T + BN + ReLU -> out fp32 (B, CO, N)
    {
        dim3 grid(NPTS / 128, CO / 128, B_SZ);
        mma_layer_kernel<CO, false><<<grid, 256, SMEM_L1>>>(
            W1, Y0, out, nullptr, g1, b1, mu1, var1, nullptr, nullptr, nullptr);
    }
    (void)in_sizes; (void)n_in; (void)out_size;
}

// round 17
// speedup vs baseline: 1.2813x; 1.0123x over previous
#include <cuda_runtime.h>
#include <cuda_fp16.h>
#include <cstdint>

#define B_SZ 8
#define NPTS 16384
#define MSRC 1024
#define C1   128
#define C2   256
#define CIN  384
#define CO   256
#define BN_EPS 1e-5f

// ---------------------------------------------------------------------------
// Scratch (allocation-free)
// ---------------------------------------------------------------------------
__device__ __align__(256) float  g_Zt [(size_t)B_SZ * MSRC * CO];
__device__ __align__(256) int4   g_nni[(size_t)B_SZ * NPTS];
__device__ __align__(256) float4 g_nnw[(size_t)B_SZ * NPTS];
__device__ __align__(256) __half g_W0 [CO * C1];
__device__ __align__(256) __half g_W1 [CO * CO];
__device__ __align__(256) __half g_T  [(size_t)B_SZ * NPTS * C1];   // tfeat^T fp16
__device__ __align__(256) __half g_Y0 [(size_t)B_SZ * NPTS * CO];   // Y0^T fp16

// ---------------------------------------------------------------------------
// PTX helpers (sm_100-safe)
// ---------------------------------------------------------------------------
__device__ __forceinline__ uint32_t smem_u32(const void* p) {
    uint32_t a;
    asm("{ .reg .u64 t; cvta.to.shared.u64 t, %1; cvt.u32.u64 %0, t; }" : "=r"(a) : "l"(p));
    return a;
}
#define CP16(dst, src) \
    asm volatile("cp.async.cg.shared.global [%0], [%1], 16;" :: "r"(dst), "l"(src))
#define CP_COMMIT() asm volatile("cp.async.commit_group;" ::: "memory")
#define CP_WAIT(n)  asm volatile("cp.async.wait_group %0;" :: "n"(n) : "memory")

#define LDSM4(r, addr) \
    asm volatile("ldmatrix.sync.aligned.m8n8.x4.shared.b16 {%0,%1,%2,%3}, [%4];" \
        : "=r"((r)[0]), "=r"((r)[1]), "=r"((r)[2]), "=r"((r)[3]) : "r"(addr))

#define MMA_F16(d, a, b0, b1) \
    asm volatile("mma.sync.aligned.m16n8k16.row.col.f32.f16.f16.f32 " \
        "{%0,%1,%2,%3}, {%4,%5,%6,%7}, {%8,%9}, {%0,%1,%2,%3};" \
        : "+f"((d)[0]), "+f"((d)[1]), "+f"((d)[2]), "+f"((d)[3]) \
        : "r"((a)[0]), "r"((a)[1]), "r"((a)[2]), "r"((a)[3]), "r"(b0), "r"(b1))

// ---------------------------------------------------------------------------
// three_nn: 2 target points per thread. Grid: (NPTS/512, B), 256 threads.
// ---------------------------------------------------------------------------
__global__ void __launch_bounds__(256)
three_nn_kernel(const float* __restrict__ target, const float* __restrict__ source,
                int4* __restrict__ nni, float4* __restrict__ nnw)
{
    const int b = blockIdx.y, t = threadIdx.x;
    const int ia = blockIdx.x * 512 + t;
    const int ib = ia + 256;
    __shared__ float4 s[MSRC];
    const float* src = source + (size_t)b * MSRC * 3;
    for (int j = t; j < MSRC; j += 256) {
        const float x = src[j * 3 + 0], y = src[j * 3 + 1], z = src[j * 3 + 2];
        s[j] = make_float4(x, y, z, x * x + y * y + z * z);
    }
    __syncthreads();

    const float* tpa = target + ((size_t)b * NPTS + ia) * 3;
    const float* tpb = target + ((size_t)b * NPTS + ib) * 3;
    const float pax = tpa[0], pay = tpa[1], paz = tpa[2];
    const float pbx = tpb[0], pby = tpb[1], pbz = tpb[2];
    const float qax = -2.0f * pax, qay = -2.0f * pay, qaz = -2.0f * paz;
    const float qbx = -2.0f * pbx, qby = -2.0f * pby, qbz = -2.0f * pbz;

    float a0 = 3.4e38f, a1 = 3.4e38f, a2 = 3.4e38f;
    float f0 = 3.4e38f, f1 = 3.4e38f, f2 = 3.4e38f;
    int   ja0 = 0, ja1 = 0, ja2 = 0, jb0 = 0, jb1 = 0, jb2 = 0;
    #pragma unroll 4
    for (int j = 0; j < MSRC; j++) {
        const float4 v = s[j];
        const float ea = fmaf(qax, v.x, fmaf(qay, v.y, fmaf(qaz, v.z, v.w)));
        const float eb = fmaf(qbx, v.x, fmaf(qby, v.y, fmaf(qbz, v.z, v.w)));
        if (ea < a0)      { a2 = a1; ja2 = ja1; a1 = a0; ja1 = ja0; a0 = ea; ja0 = j; }
        else if (ea < a1) { a2 = a1; ja2 = ja1; a1 = ea; ja1 = j; }
        else if (ea < a2) { a2 = ea; ja2 = j; }
        if (eb < f0)      { f2 = f1; jb2 = jb1; f1 = f0; jb1 = jb0; f0 = eb; jb0 = j; }
        else if (eb < f1) { f2 = f1; jb2 = jb1; f1 = eb; jb1 = j; }
        else if (eb < f2) { f2 = eb; jb2 = j; }
    }
    {
        float d[3]; const int jj[3] = {ja0, ja1, ja2};
        #pragma unroll
        for (int k = 0; k < 3; k++) {
            const float4 v = s[jj[k]];
            const float dx = pax - v.x, dy = pay - v.y, dz = paz - v.z;
            d[k] = dx * dx + dy * dy + dz * dz;
        }
        const float r0 = 1.0f / (d[0] + 1e-8f), r1 = 1.0f / (d[1] + 1e-8f), r2 = 1.0f / (d[2] + 1e-8f);
        const float rs = 1.0f / (r0 + r1 + r2);
        nni[(size_t)b * NPTS + ia] = make_int4(ja0, ja1, ja2, 0);
        nnw[(size_t)b * NPTS + ia] = make_float4(r0 * rs, r1 * rs, r2 * rs, 0.0f);
    }
    {
        float d[3]; const int jj[3] = {jb0, jb1, jb2};
        #pragma unroll
        for (int k = 0; k < 3; k++) {
            const float4 v = s[jj[k]];
            const float dx = pbx - v.x, dy = pby - v.y, dz = pbz - v.z;
            d[k] = dx * dx + dy * dy + dz * dz;
        }
        const float r0 = 1.0f / (d[0] + 1e-8f), r1 = 1.0f / (d[1] + 1e-8f), r2 = 1.0f / (d[2] + 1e-8f);
        const float rs = 1.0f / (r0 + r1 + r2);
        nni[(size_t)b * NPTS + ib] = make_int4(jb0, jb1, jb2, 0);
        nnw[(size_t)b * NPTS + ib] = make_float4(r0 * rs, r1 * rs, r2 * rs, 0.0f);
    }
}

// ---------------------------------------------------------------------------
// Zt = (w0[:, :256] @ sfeat)^T per batch (fp32 — keeps interp path exact)
// ---------------------------------------------------------------------------
__global__ void __launch_bounds__(256, 2)
zt_kernel(const float* __restrict__ w0, const float* __restrict__ sfeat, float* __restrict__ Zt)
{
    constexpr int BK = 16, TM = 8, TN = 8;
    __shared__ float Ss[BK][128];
    __shared__ float Ws[BK][128];
    const int b = blockIdx.z, J0 = blockIdx.x * 128, O0 = blockIdx.y * 128;
    const float* sf = sfeat + (size_t)b * C2 * MSRC;
    const int tid = threadIdx.x;
    const int rowO = tid >> 2, colK = (tid & 3) * 4;
    const int rowK = tid >> 5, colJ = (tid & 31) * 4;
    const int tj = (tid >> 4) * TM, to = (tid & 15) * TN;
    float acc[TM][TN];
    #pragma unroll
    for (int i = 0; i < TM; i++)
        #pragma unroll
        for (int j = 0; j < TN; j++) acc[i][j] = 0.0f;
    for (int k0 = 0; k0 < C2; k0 += BK) {
        #pragma unroll
        for (int p = 0; p < 2; p++) {
            const int r = rowO + p * 64;
            const float4 v = *(const float4*)(w0 + (size_t)(O0 + r) * CIN + k0 + colK);
            Ws[colK + 0][r] = v.x; Ws[colK + 1][r] = v.y;
            Ws[colK + 2][r] = v.z; Ws[colK + 3][r] = v.w;
        }
        #pragma unroll
        for (int p = 0; p < 2; p++) {
            const int r = rowK + p * 8;
            *(float4*)&Ss[r][colJ] = *(const float4*)(sf + (size_t)(k0 + r) * MSRC + J0 + colJ);
        }
        __syncthreads();
        #pragma unroll
        for (int kk = 0; kk < BK; kk++) {
            float a[TM], w[TN];
            #pragma unroll
            for (int i = 0; i < TM; i += 4) *(float4*)&a[i] = *(const float4*)&Ss[kk][tj + i];
            #pragma unroll
            for (int j = 0; j < TN; j += 4) *(float4*)&w[j] = *(const float4*)&Ws[kk][to + j];
            #pragma unroll
            for (int i = 0; i < TM; i++)
                #pragma unroll
                for (int j = 0; j < TN; j++) acc[i][j] = fmaf(a[i], w[j], acc[i][j]);
        }
        __syncthreads();
    }
    float* Zb = Zt + (size_t)b * MSRC * CO;
    #pragma unroll
    for (int i = 0; i < TM; i++)
        #pragma unroll
        for (int j = 0; j < TN; j += 4) {
            float4 v = make_float4(acc[i][j], acc[i][j+1], acc[i][j+2], acc[i][j+3]);
            *(float4*)(Zb + (size_t)(J0 + tj + i) * CO + O0 + to + j) = v;
        }
}

// ---------------------------------------------------------------------------
// Merged prep kernel: blocks [0, 16384) = tfeat transpose (B,C1,N)->(B,N,C1)
// fp16; blocks [16384, 16384+384) = weight converts (W0 slice + W1).
// Both bodies are trivial (<= ~24 regs) so merging costs nothing.
// ---------------------------------------------------------------------------
__global__ void __launch_bounds__(256)
prep_kernel(const float* __restrict__ tfeat, __half* __restrict__ T,
            const float* __restrict__ w0, const float* __restrict__ w1,
            __half* __restrict__ W0, __half* __restrict__ W1)
{
    __shared__ float sm[32][33];
    const int id = blockIdx.x;
    if (id < 16384) {
        const int nb = id & 511, cb = (id >> 9) & 3, b = id >> 11;
        const int n0 = nb * 32, c0 = cb * 32;
        const int tx = threadIdx.x & 31, ty = threadIdx.x >> 5;
        const float* src = tfeat + (size_t)b * C1 * NPTS;
        #pragma unroll
        for (int i = 0; i < 4; i++) {
            const int c = ty + i * 8;
            sm[c][tx] = src[(size_t)(c0 + c) * NPTS + n0 + tx];
        }
        __syncthreads();
        #pragma unroll
        for (int i = 0; i < 4; i++) {
            const int n = ty + i * 8;
            T[((size_t)b * NPTS + n0 + n) * C1 + c0 + tx] = __float2half_rn(sm[tx][n]);
        }
    } else {
        const int idx = (id - 16384) * 256 + threadIdx.x;
        if (idx < CO * C1) {
            const int o = idx / C1, k = idx % C1;
            W0[idx] = __float2half_rn(w0[(size_t)o * CIN + C2 + k]);
        } else {
            const int j = idx - CO * C1;
            if (j < CO * CO) {
                const int o = j / CO, k = j % CO;
                W1[j] = __float2half_rn(w1[(size_t)o * CO + k]);
            }
        }
    }
}

// ---------------------------------------------------------------------------
// GEMM template: fp16 single-pass, CTA 128m x 128n, BK=64, 8 warps (4m x 2n),
// cp.async double buffer, 2 CTAs/SM.
// L0GATHER: nni/nnw staged into smem via cp.async during the mainloop, BN
// scale/bias precomputed once into smem; epilogue gather + BN + ReLU -> Y0^T.
// else: BN + ReLU -> out fp32 (B, CO, N).
// ---------------------------------------------------------------------------
template<int KW, bool L0GATHER>
__global__ void __launch_bounds__(256, 2)
mma_layer_kernel(const __half* __restrict__ W, const __half* __restrict__ X,
                 float* __restrict__ outF, __half* __restrict__ outH,
                 const float* __restrict__ gam, const float* __restrict__ bet,
                 const float* __restrict__ mu,  const float* __restrict__ var,
                 const int4* __restrict__ nni, const float4* __restrict__ nnw,
                 const float* __restrict__ Zt)
{
    constexpr int KC    = KW / 64;
    constexpr int TS    = 128 * 144;
    constexpr int BUF   = 2 * TS;
    constexpr int STAGE = 2 * BUF;          // 73728: staging area (L0 only)
    extern __shared__ __align__(16) char smem[];
    const uint32_t sb = smem_u32(smem);

    const int tid = threadIdx.x, lane = tid & 31, wid = tid >> 5;
    const int wm = wid >> 1, wn = wid & 1;
    const int b = blockIdx.z, n0 = blockIdx.x * 128, m0 = blockIdx.y * 128;
    const size_t bn = (size_t)b * NPTS;

    const __half* A_g = W + (size_t)m0 * KW;
    const __half* B_g = X + (bn + n0) * KW;

    const int lr = tid >> 3;
    const int lc = (tid & 7) * 8;

    float acc[2][8][4];
    #pragma unroll
    for (int i = 0; i < 2; i++)
        #pragma unroll
        for (int j = 0; j < 8; j++)
            #pragma unroll
            for (int q = 0; q < 4; q++) acc[i][j][q] = 0.0f;

    #pragma unroll
    for (int it = 0; it < 4; it++) {
        const int r = lr + it * 32;
        const uint32_t so = (uint32_t)(r * 144 + lc * 2);
        CP16(sb + so,      A_g + (size_t)r * KW + lc);
        CP16(sb + TS + so, B_g + (size_t)r * KW + lc);
    }
    if (L0GATHER && tid < 128) {
        CP16(sb + STAGE + tid * 16,        nni + bn + n0 + tid);
        CP16(sb + STAGE + 2048 + tid * 16, nnw + bn + n0 + tid);
    }
    CP_COMMIT();

    if (L0GATHER && tid < 128) {
        const int o = m0 + tid;
        const float s = gam[o] * rsqrtf(var[o] + BN_EPS);
        ((float2*)(smem + STAGE + 4096))[tid] = make_float2(s, bet[o] - mu[o] * s);
    }

    for (int c = 0; c < KC; c++) {
        if (c + 1 < KC) {
            const int k0 = (c + 1) * 64;
            const uint32_t bufo = (uint32_t)(((c + 1) & 1) * BUF);
            #pragma unroll
            for (int it = 0; it < 4; it++) {
                const int r = lr + it * 32;
                const uint32_t so = bufo + (uint32_t)(r * 144 + lc * 2);
                CP16(sb + so,      A_g + (size_t)r * KW + k0 + lc);
                CP16(sb + TS + so, B_g + (size_t)r * KW + k0 + lc);
            }
            CP_COMMIT();
            CP_WAIT(1);
        } else {
            CP_WAIT(0);
        }
        __syncthreads();

        const uint32_t base = sb + (uint32_t)((c & 1) * BUF);
        #pragma unroll
        for (int kk = 0; kk < 4; kk++) {
            uint32_t ah[2][4];
            #pragma unroll
            for (int mt = 0; mt < 2; mt++) {
                const uint32_t ad = base
                    + (uint32_t)((wm * 32 + mt * 16 + (lane & 15)) * 144
                                 + (kk * 16 + ((lane >> 4) << 3)) * 2);
                LDSM4(ah[mt], ad);
            }
            #pragma unroll
            for (int ng = 0; ng < 4; ng++) {
                uint32_t bh[4];
                const uint32_t bd = base + TS
                    + (uint32_t)((wn * 64 + ng * 16 + (lane & 7) + ((lane >> 4) << 3)) * 144
                                 + (kk * 16 + (((lane >> 3) & 1) << 3)) * 2);
                LDSM4(bh, bd);
                #pragma unroll
                for (int mt = 0; mt < 2; mt++)
                    #pragma unroll
                    for (int hh = 0; hh < 2; hh++)
                        MMA_F16(acc[mt][ng * 2 + hh], ah[mt], bh[2 * hh], bh[2 * hh + 1]);
            }
        }
        __syncthreads();
    }

    if (!L0GATHER) {
        #pragma unroll
        for (int mt = 0; mt < 2; mt++) {
            const int o0 = m0 + wm * 32 + mt * 16 + (lane >> 2);
            const float s0 = gam[o0] * rsqrtf(var[o0] + BN_EPS);
            const float c0 = bet[o0] - mu[o0] * s0;
            const int o1 = o0 + 8;
            const float s1 = gam[o1] * rsqrtf(var[o1] + BN_EPS);
            const float c1 = bet[o1] - mu[o1] * s1;
            #pragma unroll
            for (int j = 0; j < 8; j++) {
                const int n = n0 + wn * 64 + j * 8 + (lane & 3) * 2;
                float2 v0, v1;
                v0.x = fmaxf(fmaf(acc[mt][j][0], s0, c0), 0.0f);
                v0.y = fmaxf(fmaf(acc[mt][j][1], s0, c0), 0.0f);
                v1.x = fmaxf(fmaf(acc[mt][j][2], s1, c1), 0.0f);
                v1.y = fmaxf(fmaf(acc[mt][j][3], s1, c1), 0.0f);
                *(float2*)(outF + ((size_t)b * CO + o0) * NPTS + n) = v0;
                *(float2*)(outF + ((size_t)b * CO + o1) * NPTS + n) = v1;
            }
        }
    } else {
        float* S = (float*)smem;   // 128 x 132 fp32 = 67584 < 73728 (staging safe)
        #pragma unroll
        for (int mt = 0; mt < 2; mt++) {
            const int ol = wm * 32 + mt * 16 + (lane >> 2);
            #pragma unroll
            for (int j = 0; j < 8; j++) {
                const int nl = wn * 64 + j * 8 + (lane & 3) * 2;
                S[(nl + 0) * 132 + ol]     = acc[mt][j][0];
                S[(nl + 1) * 132 + ol]     = acc[mt][j][1];
                S[(nl + 0) * 132 + ol + 8] = acc[mt][j][2];
                S[(nl + 1) * 132 + ol + 8] = acc[mt][j][3];
            }
        }
        __syncthreads();

        const int4*   s_ji = (const int4*)(smem + STAGE);
        const float4* s_jw = (const float4*)(smem + STAGE + 2048);
        const float*  s_bn = (const float*)(smem + STAGE + 4096);
        const float* Zb = Zt + (size_t)b * MSRC * CO;
        #pragma unroll 4
        for (int it = 0; it < 16; it++) {
            const int item = tid + it * 256;
            const int nl = item >> 5, o4 = (item & 31) * 4;
            const int n = n0 + nl, o = m0 + o4;
            const int4   ji = s_ji[nl];
            const float4 jw = s_jw[nl];
            const float4 z0 = *(const float4*)(Zb + (size_t)ji.x * CO + o);
            const float4 z1 = *(const float4*)(Zb + (size_t)ji.y * CO + o);
            const float4 z2 = *(const float4*)(Zb + (size_t)ji.z * CO + o);
            float4 v = *(float4*)(S + nl * 132 + o4);
            v.x += jw.x * z0.x + jw.y * z1.x + jw.z * z2.x;
            v.y += jw.x * z0.y + jw.y * z1.y + jw.z * z2.y;
            v.z += jw.x * z0.z + jw.y * z1.z + jw.z * z2.z;
            v.w += jw.x * z0.w + jw.y * z1.w + jw.z * z2.w;
            const float4 p0 = *(const float4*)(s_bn + o4 * 2);
            const float4 p1 = *(const float4*)(s_bn + o4 * 2 + 4);
            union { __half h[4]; uint2 u; } H;
            H.h[0] = __float2half_rn(fmaxf(fmaf(v.x, p0.x, p0.y), 0.0f));
            H.h[1] = __float2half_rn(fmaxf(fmaf(v.y, p0.z, p0.w), 0.0f));
            H.h[2] = __float2half_rn(fmaxf(fmaf(v.z, p1.x, p1.y), 0.0f));
            H.h[3] = __float2half_rn(fmaxf(fmaf(v.w, p1.z, p1.w), 0.0f));
            *(uint2*)(outH + (bn + n) * CO + o) = H.u;
        }
    }
}

// ---------------------------------------------------------------------------
extern "C" void kernel_launch(void* const* d_in, const int* in_sizes, int n_in,
                              void* d_out, int out_size)
{
    const float* target = (const float*)d_in[0];
    const float* source = (const float*)d_in[1];
    const float* tfeat  = (const float*)d_in[2];
    const float* sfeat  = (const float*)d_in[3];
    const float* w0     = (const float*)d_in[4];
    const float* g0     = (const float*)d_in[5];
    const float* b0     = (const float*)d_in[6];
    const float* mu0    = (const float*)d_in[7];
    const float* var0   = (const float*)d_in[8];
    const float* w1     = (const float*)d_in[9];
    const float* g1     = (const float*)d_in[10];
    const float* b1     = (const float*)d_in[11];
    const float* mu1    = (const float*)d_in[12];
    const float* var1   = (const float*)d_in[13];
    float* out = (float*)d_out;

    float*  Zt;  cudaGetSymbolAddress((void**)&Zt,  g_Zt);
    int4*   nni; cudaGetSymbolAddress((void**)&nni, g_nni);
    float4* nnw; cudaGetSymbolAddress((void**)&nnw, g_nnw);
    __half *W0, *W1, *T, *Y0;
    cudaGetSymbolAddress((void**)&W0, g_W0); cudaGetSymbolAddress((void**)&W1, g_W1);
    cudaGetSymbolAddress((void**)&T,  g_T);  cudaGetSymbolAddress((void**)&Y0, g_Y0);

    constexpr int SMEM_L1 = 2 * 2 * 128 * 144;        // 73728
    constexpr int SMEM_L0 = SMEM_L1 + 4096 + 1024;    // + nni/nnw + BN stage
    cudaFuncSetAttribute(mma_layer_kernel<C1, true>,
                         cudaFuncAttributeMaxDynamicSharedMemorySize, SMEM_L0);
    cudaFuncSetAttribute(mma_layer_kernel<CO, false>,
                         cudaFuncAttributeMaxDynamicSharedMemorySize, SMEM_L1);

    // 1) three_nn (2 points/thread)
    {
        dim3 grid(NPTS / 512, B_SZ);
        three_nn_kernel<<<grid, 256>>>(target, source, nni, nnw);
    }
    // 2) Zt = (w0[:, :256] @ sfeat)^T
    {
        dim3 grid(MSRC / 128, CO / 128, B_SZ);
        zt_kernel<<<grid, 256>>>(w0, sfeat, Zt);
    }
    // 3) merged prep: tfeat transpose (16384 blk) + weight converts (384 blk)
    prep_kernel<<<16384 + 384, 256>>>(tfeat, T, w0, w1, W0, W1);
    // 4) layer 0 (now launch #4 -> ncu capture slot): W0 @ T^T + gather + BN + ReLU
    {
        dim3 grid(NPTS / 128, CO / 128, B_SZ);
        mma_layer_kernel<C1, true><<<grid, 256, SMEM_L0>>>(
            W0, T, nullptr, Y0, g0, b0, mu0, var0, nni, nnw, Zt);
    }
    // 5) layer 1: W1 @ Y0^T + BN + ReLU -> out fp32 (B, CO, N)
    {
        dim3 grid(NPTS / 128, CO / 128, B_SZ);
        mma_layer_kernel<CO, false><<<grid, 256, SMEM_L1>>>(
            W1, Y0, out, nullptr, g1, b1, mu1, var1, nullptr, nullptr, nullptr);
    }
    (void)in_sizes; (void)n_in; (void)out_size;
}